// round 6
// baseline (speedup 1.0000x reference)
#include <cuda_runtime.h>
#include <math.h>
#include <stdint.h>

#define NB   64
#define TT   1024
#define INW  64
#define H1   512
#define H2   256

// ---------------- scratch (static device globals; no allocation) ----------------
__device__ float g_out1[(size_t)NB * TT * H1];   // 134 MB  h1 sequence
__device__ float g_out2[(size_t)NB * TT * H2];   // 67 MB   h2 sequence
__device__ float g_ctx [(size_t)NB * TT * H2];   // 67 MB   attention contexts
__device__ float g_c1[NB * H1];
__device__ float g_c2[NB * H2];
__device__ float g_fc1T[512 * 128];              // fc1_w transposed [k][j]
__device__ float g_fc2T[128 * 51];               // fc2_w transposed [k][j]
__device__ unsigned g_bar1;
__device__ unsigned g_bar2;

__global__ void reset_kernel() { g_bar1 = 0u; g_bar2 = 0u; }

__global__ void prep_kernel(const float* __restrict__ fc1w, const float* __restrict__ fc2w) {
    int i = blockIdx.x * blockDim.x + threadIdx.x;
    if (i < 128 * 512) { int j = i / 512, k = i % 512; g_fc1T[k * 128 + j] = fc1w[i]; }
    if (i < 51 * 128)  { int j = i / 128, k = i % 128; g_fc2T[k * 51 + j] = fc2w[i]; }
}

__device__ __forceinline__ float sigf(float x) { return 1.f / (1.f + __expf(-x)); }

// ============================ LSTM layer 1 ============================
// grid 128 CTAs x 256 thr, all resident. CTA b owns hidden cols [4b,4b+4).
// thread: cI = tid&15 (gate=cI>>2, hcl=cI&3), rowgrp = tid>>4, rows = rowgrp*4..+3
__global__ void __launch_bounds__(256, 1)
lstm1_kernel(const float* __restrict__ x,
             const float* __restrict__ Wih, const float* __restrict__ Whh,
             const float* __restrict__ bih, const float* __restrict__ bhh,
             float* __restrict__ dout)
{
    __shared__ float sW[16 * 580];               // 16 gate rows x 576 (pad 580)
    const int tid = threadIdx.x;
    const int cI = tid & 15;
    const int rowgrp = tid >> 4;
    const int gate = cI >> 2;
    const int hcl = cI & 3;
    const int hc = blockIdx.x * 4 + hcl;
    const int grow = gate * H1 + hc;

    // stage weights (constant over t): [x part 64 | h part 512]
    for (int i = tid; i < 16 * 576; i += 256) {
        int r = i / 576, k = i - r * 576;
        int gr = (r >> 2) * H1 + blockIdx.x * 4 + (r & 3);
        sW[r * 580 + k] = (k < INW) ? Wih[gr * INW + k] : Whh[gr * H1 + (k - INW)];
    }
    const float bias = bih[grow] + bhh[grow];
    __syncthreads();

    const int r0 = rowgrp * 4;
    const unsigned lane = tid & 31;
    const unsigned sl0 = lane & 19u;             // keeps (rowgrp parity | hcl)
    const bool isg0 = ((lane & 12u) == 0u);

    for (int t = 0; t < TT; ++t) {
        float acc[4];
#pragma unroll
        for (int j = 0; j < 4; ++j) acc[j] = bias;

        const float4* wv = (const float4*)(sW + cI * 580);
        // ---- x part (k = 0..63) ----
        {
            const float4* xr0 = (const float4*)(x + ((size_t)(r0 + 0) * TT + t) * INW);
            const float4* xr1 = (const float4*)(x + ((size_t)(r0 + 1) * TT + t) * INW);
            const float4* xr2 = (const float4*)(x + ((size_t)(r0 + 2) * TT + t) * INW);
            const float4* xr3 = (const float4*)(x + ((size_t)(r0 + 3) * TT + t) * INW);
#pragma unroll
            for (int k4 = 0; k4 < 16; ++k4) {
                float4 w = wv[k4];
                float4 v;
                v = xr0[k4]; acc[0] += w.x*v.x + w.y*v.y + w.z*v.z + w.w*v.w;
                v = xr1[k4]; acc[1] += w.x*v.x + w.y*v.y + w.z*v.z + w.w*v.w;
                v = xr2[k4]; acc[2] += w.x*v.x + w.y*v.y + w.z*v.z + w.w*v.w;
                v = xr3[k4]; acc[3] += w.x*v.x + w.y*v.y + w.z*v.z + w.w*v.w;
            }
        }
        // ---- h part (k = 64..575) reads h[t-1] ----
        if (t > 0) {
            const float4* h0p = (const float4*)(g_out1 + ((size_t)(r0 + 0) * TT + (t - 1)) * H1);
            const float4* h1p = (const float4*)(g_out1 + ((size_t)(r0 + 1) * TT + (t - 1)) * H1);
            const float4* h2p = (const float4*)(g_out1 + ((size_t)(r0 + 2) * TT + (t - 1)) * H1);
            const float4* h3p = (const float4*)(g_out1 + ((size_t)(r0 + 3) * TT + (t - 1)) * H1);
#pragma unroll 8
            for (int k4 = 0; k4 < 128; ++k4) {
                float4 w = wv[16 + k4];
                float4 v;
                v = h0p[k4]; acc[0] += w.x*v.x + w.y*v.y + w.z*v.z + w.w*v.w;
                v = h1p[k4]; acc[1] += w.x*v.x + w.y*v.y + w.z*v.z + w.w*v.w;
                v = h2p[k4]; acc[2] += w.x*v.x + w.y*v.y + w.z*v.z + w.w*v.w;
                v = h3p[k4]; acc[3] += w.x*v.x + w.y*v.y + w.z*v.z + w.w*v.w;
            }
        }

        // gather the 4 gates per hidden unit via warp shuffles
#pragma unroll
        for (int j = 0; j < 4; ++j) {
            float a = acc[j];
            float xi = __shfl_sync(0xffffffffu, a, sl0 | 0u);
            float xf = __shfl_sync(0xffffffffu, a, sl0 | 4u);
            float xg = __shfl_sync(0xffffffffu, a, sl0 | 8u);
            float xo = __shfl_sync(0xffffffffu, a, sl0 | 12u);
            if (isg0) {
                int n = r0 + j;
                float cp = (t == 0) ? 0.f : g_c1[n * H1 + hc];
                float c = sigf(xf) * cp + sigf(xi) * tanhf(xg);
                g_c1[n * H1 + hc] = c;
                float h = sigf(xo) * tanhf(c);
                g_out1[((size_t)n * TT + t) * H1 + hc] = h;
                if (t == TT - 1) {
                    dout[65536 + n * H1 + hc] = h;   // h1 final
                    dout[98304 + n * H1 + hc] = c;   // c1 final
                }
            }
        }

        // grid barrier between steps
        if (t < TT - 1) {
            __threadfence();
            __syncthreads();
            if (tid == 0) {
                atomicAdd(&g_bar1, 1u);
                unsigned target = 128u * (unsigned)(t + 1);
                while (*(volatile unsigned*)&g_bar1 < target) {}
            }
            __syncthreads();
        }
    }
}

// ============================ LSTM layer 2 ============================
// grid 128 CTAs x 256 thr. CTA b owns hidden cols [2b,2b+2).
// thread: cI = tid&7 (gate=cI>>1, hcl=cI&1), rowgrp = tid>>3, rows = rowgrp*2..+1
__global__ void __launch_bounds__(256, 1)
lstm2_kernel(const float* __restrict__ Wih, const float* __restrict__ Whh,
             const float* __restrict__ bih, const float* __restrict__ bhh,
             float* __restrict__ dout)
{
    __shared__ float sW[8 * 772];                // 8 gate rows x 768 (pad 772)
    const int tid = threadIdx.x;
    const int cI = tid & 7;
    const int rowgrp = tid >> 3;
    const int gate = cI >> 1;
    const int hcl = cI & 1;
    const int hc = blockIdx.x * 2 + hcl;
    const int grow = gate * H2 + hc;

    for (int i = tid; i < 8 * 768; i += 256) {
        int r = i / 768, k = i - r * 768;
        int gr = (r >> 1) * H2 + blockIdx.x * 2 + (r & 1);
        sW[r * 772 + k] = (k < H1) ? Wih[gr * H1 + k] : Whh[gr * H2 + (k - H1)];
    }
    const float bias = bih[grow] + bhh[grow];
    __syncthreads();

    const int r0 = rowgrp * 2;
    const unsigned lane = tid & 31;
    const unsigned sl0 = lane & 25u;             // keeps (rowgrp bits | hcl)
    const bool isg0 = ((lane & 6u) == 0u);

    for (int t = 0; t < TT; ++t) {
        float acc[2] = {bias, bias};
        const float4* wv = (const float4*)(sW + cI * 772);
        // ---- h1[t] part (k = 0..511) ----
        {
            const float4* a0p = (const float4*)(g_out1 + ((size_t)(r0 + 0) * TT + t) * H1);
            const float4* a1p = (const float4*)(g_out1 + ((size_t)(r0 + 1) * TT + t) * H1);
#pragma unroll 8
            for (int k4 = 0; k4 < 128; ++k4) {
                float4 w = wv[k4];
                float4 v;
                v = a0p[k4]; acc[0] += w.x*v.x + w.y*v.y + w.z*v.z + w.w*v.w;
                v = a1p[k4]; acc[1] += w.x*v.x + w.y*v.y + w.z*v.z + w.w*v.w;
            }
        }
        // ---- h2[t-1] part (k = 512..767) ----
        if (t > 0) {
            const float4* b0p = (const float4*)(g_out2 + ((size_t)(r0 + 0) * TT + (t - 1)) * H2);
            const float4* b1p = (const float4*)(g_out2 + ((size_t)(r0 + 1) * TT + (t - 1)) * H2);
#pragma unroll 8
            for (int k4 = 0; k4 < 64; ++k4) {
                float4 w = wv[128 + k4];
                float4 v;
                v = b0p[k4]; acc[0] += w.x*v.x + w.y*v.y + w.z*v.z + w.w*v.w;
                v = b1p[k4]; acc[1] += w.x*v.x + w.y*v.y + w.z*v.z + w.w*v.w;
            }
        }

#pragma unroll
        for (int j = 0; j < 2; ++j) {
            float a = acc[j];
            float xi = __shfl_sync(0xffffffffu, a, sl0 | 0u);
            float xf = __shfl_sync(0xffffffffu, a, sl0 | 2u);
            float xg = __shfl_sync(0xffffffffu, a, sl0 | 4u);
            float xo = __shfl_sync(0xffffffffu, a, sl0 | 6u);
            if (isg0) {
                int n = r0 + j;
                float cp = (t == 0) ? 0.f : g_c2[n * H2 + hc];
                float c = sigf(xf) * cp + sigf(xi) * tanhf(xg);
                g_c2[n * H2 + hc] = c;
                float h = sigf(xo) * tanhf(c);
                g_out2[((size_t)n * TT + t) * H2 + hc] = h;
                if (t == TT - 1) {
                    dout[131072 + n * H2 + hc] = h;  // h2 final
                    dout[147456 + n * H2 + hc] = c;  // c2 final
                }
            }
        }

        if (t < TT - 1) {
            __threadfence();
            __syncthreads();
            if (tid == 0) {
                atomicAdd(&g_bar2, 1u);
                unsigned target = 128u * (unsigned)(t + 1);
                while (*(volatile unsigned*)&g_bar2 < target) {}
            }
            __syncthreads();
        }
    }
}

// ============================ causal attention ============================
// warp per (n,t) query row, online softmax, unscaled scores.
__global__ void __launch_bounds__(256)
attn_kernel()
{
    const int lane = threadIdx.x & 31;
    const int gw = blockIdx.x * (blockDim.x >> 5) + (threadIdx.x >> 5);
    const int nw = gridDim.x * (blockDim.x >> 5);

    for (int row = gw; row < NB * TT; row += nw) {
        const int n = row >> 10;
        const int t = row & 1023;
        const float* bp = g_out2 + (size_t)n * TT * H2;
        const float4* qp = (const float4*)(bp + (size_t)t * H2);
        const float4 qa = qp[lane];
        const float4 qb = qp[lane + 32];

        float m = -1e30f, l = 0.f;
        float4 accA = make_float4(0.f, 0.f, 0.f, 0.f);
        float4 accB = make_float4(0.f, 0.f, 0.f, 0.f);

        for (int s = 0; s <= t; ++s) {
            const float4* kp = (const float4*)(bp + (size_t)s * H2);
            float4 ka = kp[lane];
            float4 kb = kp[lane + 32];
            float p = qa.x*ka.x + qa.y*ka.y + qa.z*ka.z + qa.w*ka.w
                    + qb.x*kb.x + qb.y*kb.y + qb.z*kb.z + qb.w*kb.w;
            p += __shfl_xor_sync(0xffffffffu, p, 16);
            p += __shfl_xor_sync(0xffffffffu, p, 8);
            p += __shfl_xor_sync(0xffffffffu, p, 4);
            p += __shfl_xor_sync(0xffffffffu, p, 2);
            p += __shfl_xor_sync(0xffffffffu, p, 1);
            float nm = fmaxf(m, p);
            float e  = __expf(p - nm);
            float sc = __expf(m - nm);
            l = l * sc + e;
            accA.x = accA.x*sc + e*ka.x; accA.y = accA.y*sc + e*ka.y;
            accA.z = accA.z*sc + e*ka.z; accA.w = accA.w*sc + e*ka.w;
            accB.x = accB.x*sc + e*kb.x; accB.y = accB.y*sc + e*kb.y;
            accB.z = accB.z*sc + e*kb.z; accB.w = accB.w*sc + e*kb.w;
            m = nm;
        }
        float inv = 1.f / l;
        float4* op = (float4*)(g_ctx + (size_t)row * H2);
        op[lane]      = make_float4(accA.x*inv, accA.y*inv, accA.z*inv, accA.w*inv);
        op[lane + 32] = make_float4(accB.x*inv, accB.y*inv, accB.z*inv, accB.w*inv);
    }
}

// ============================ MLP head ============================
// 16-row tiles: concat(ctx, out2) -> fc1(128,relu) -> fc2(51,relu) -> fc3(1)
__global__ void __launch_bounds__(128)
mlp_kernel(const float* __restrict__ fc1b,
           const float* __restrict__ fc2b,
           const float* __restrict__ fc3w, const float* __restrict__ fc3b,
           float* __restrict__ dout)
{
    __shared__ float sIn[16][512];
    __shared__ float sH1[16][128];
    __shared__ float sH2[16][52];
    const int tid = threadIdx.x;

    for (int tile = blockIdx.x; tile < (NB * TT) / 16; tile += gridDim.x) {
        const int row0 = tile * 16;
        for (int i = tid; i < 16 * 512; i += 128) {
            int r = i >> 9, c = i & 511;
            size_t row = (size_t)(row0 + r);
            sIn[r][c] = (c < 256) ? g_ctx[row * 256 + c] : g_out2[row * 256 + (c - 256)];
        }
        __syncthreads();

        // fc1: thread = output j (128)
        {
            float acc[16];
            float b = fc1b[tid];
#pragma unroll
            for (int r = 0; r < 16; ++r) acc[r] = b;
            for (int k = 0; k < 512; ++k) {
                float w = g_fc1T[k * 128 + tid];
#pragma unroll
                for (int r = 0; r < 16; ++r) acc[r] = fmaf(w, sIn[r][k], acc[r]);
            }
#pragma unroll
            for (int r = 0; r < 16; ++r) sH1[r][tid] = fmaxf(acc[r], 0.f);
        }
        __syncthreads();

        // fc2: threads 0..50
        if (tid < 51) {
            float acc[16];
            float b = fc2b[tid];
#pragma unroll
            for (int r = 0; r < 16; ++r) acc[r] = b;
            for (int k = 0; k < 128; ++k) {
                float w = g_fc2T[k * 51 + tid];
#pragma unroll
                for (int r = 0; r < 16; ++r) acc[r] = fmaf(w, sH1[r][k], acc[r]);
            }
#pragma unroll
            for (int r = 0; r < 16; ++r) sH2[r][tid] = fmaxf(acc[r], 0.f);
        }
        __syncthreads();

        // fc3: threads 0..15, one row each
        if (tid < 16) {
            float s = fc3b[0];
            for (int k = 0; k < 51; ++k) s = fmaf(fc3w[k], sH2[tid][k], s);
            dout[row0 + tid] = s;
        }
        __syncthreads();
    }
}

// ============================ launch ============================
extern "C" void kernel_launch(void* const* d_in, const int* in_sizes, int n_in,
                              void* d_out, int out_size)
{
    const float* x     = (const float*)d_in[0];
    const float* Wih1  = (const float*)d_in[1];
    const float* Whh1  = (const float*)d_in[2];
    const float* bih1  = (const float*)d_in[3];
    const float* bhh1  = (const float*)d_in[4];
    const float* Wih2  = (const float*)d_in[5];
    const float* Whh2  = (const float*)d_in[6];
    const float* bih2  = (const float*)d_in[7];
    const float* bhh2  = (const float*)d_in[8];
    const float* fc1w  = (const float*)d_in[9];
    const float* fc1b  = (const float*)d_in[10];
    const float* fc2w  = (const float*)d_in[11];
    const float* fc2b  = (const float*)d_in[12];
    const float* fc3w  = (const float*)d_in[13];
    const float* fc3b  = (const float*)d_in[14];
    float* out = (float*)d_out;

    reset_kernel<<<1, 1>>>();
    prep_kernel<<<(128 * 512 + 255) / 256, 256>>>(fc1w, fc2w);
    lstm1_kernel<<<128, 256>>>(x, Wih1, Whh1, bih1, bhh1, out);
    lstm2_kernel<<<128, 256>>>(Wih2, Whh2, bih2, bhh2, out);
    attn_kernel<<<592, 256>>>();
    mlp_kernel<<<1024, 128>>>(fc1b, fc2b, fc3w, fc3b, out);
}

// round 7
// speedup vs baseline: 1.4867x; 1.4867x over previous
#include <cuda_runtime.h>
#include <math.h>
#include <stdint.h>

typedef unsigned long long ull;

#define NB   64
#define TT   1024
#define INW  64
#define H1   512
#define H2   256

#define SW1  580   // lstm1 weight row stride (floats)
#define SA1  588   // lstm1 act row stride  (floats)  -> conflict-free act LDS
#define SW2  772   // lstm2 weight row stride
#define SA2  772   // lstm2 act row stride

// ---------------- scratch (static device globals; no allocation) ----------------
__device__ float g_out1[(size_t)NB * TT * H1];   // h1 sequence
__device__ float g_out2[(size_t)NB * TT * H2];   // h2 sequence
__device__ float g_ctx [(size_t)NB * TT * H2];   // attention contexts
__device__ float g_fc1T[512 * 128];
__device__ float g_fc2T[128 * 51];
__device__ unsigned g_bar1;
__device__ unsigned g_bar2;

__global__ void reset_kernel() { g_bar1 = 0u; g_bar2 = 0u; }

__global__ void prep_kernel(const float* __restrict__ fc1w, const float* __restrict__ fc2w) {
    int i = blockIdx.x * blockDim.x + threadIdx.x;
    if (i < 128 * 512) { int j = i / 512, k = i % 512; g_fc1T[k * 128 + j] = fc1w[i]; }
    if (i < 51 * 128)  { int j = i / 128, k = i % 128; g_fc2T[k * 51 + j] = fc2w[i]; }
}

// ---------------- helpers ----------------
__device__ __forceinline__ float sigf(float x) { return 1.f / (1.f + __expf(-x)); }

__device__ __forceinline__ uint32_t s2u(const void* p) {
    uint32_t a;
    asm("{ .reg .u64 t; cvta.to.shared.u64 t, %1; cvt.u32.u64 %0, t; }" : "=r"(a) : "l"(p));
    return a;
}
__device__ __forceinline__ void cp16(uint32_t dst, const void* src) {
    asm volatile("cp.async.cg.shared.global [%0], [%1], 16;" :: "r"(dst), "l"(src));
}
__device__ __forceinline__ void cpcommit() {
    asm volatile("cp.async.commit_group;" ::: "memory");
}
__device__ __forceinline__ void cpwait(int n) {
    switch (n) {
        case 0:  asm volatile("cp.async.wait_group 0;"  ::: "memory"); break;
        case 1:  asm volatile("cp.async.wait_group 1;"  ::: "memory"); break;
        case 2:  asm volatile("cp.async.wait_group 2;"  ::: "memory"); break;
        case 3:  asm volatile("cp.async.wait_group 3;"  ::: "memory"); break;
        case 4:  asm volatile("cp.async.wait_group 4;"  ::: "memory"); break;
        case 5:  asm volatile("cp.async.wait_group 5;"  ::: "memory"); break;
        case 6:  asm volatile("cp.async.wait_group 6;"  ::: "memory"); break;
        case 7:  asm volatile("cp.async.wait_group 7;"  ::: "memory"); break;
        case 8:  asm volatile("cp.async.wait_group 8;"  ::: "memory"); break;
        case 9:  asm volatile("cp.async.wait_group 9;"  ::: "memory"); break;
        case 10: asm volatile("cp.async.wait_group 10;" ::: "memory"); break;
        default: asm volatile("cp.async.wait_group 11;" ::: "memory"); break;
    }
}
__device__ __forceinline__ ull fma2(ull a, ull b, ull c) {
    ull d;
    asm("fma.rn.f32x2 %0, %1, %2, %3;" : "=l"(d) : "l"(a), "l"(b), "l"(c));
    return d;
}
__device__ __forceinline__ float psum(ull a) {
    return __int_as_float((int)(a & 0xffffffffULL)) + __int_as_float((int)(a >> 32));
}

// ============================ LSTM layer 1 ============================
// 128 CTAs x 256 thr, 1/SM. CTA owns 4 hidden cols (16 gate rows), K=576.
// thread tile: 2 gate rows (gI=tid&7) x 2 batch rows (rp=tid>>3).
__device__ __forceinline__ void load1(int c, int t, const float* __restrict__ x, uint32_t aB) {
    const int tid = threadIdx.x;
#pragma unroll
    for (int j = 0; j < 4; ++j) {
        int o = j * 256 + tid;
        int row = o >> 4, f4 = o & 15;
        const float* src = (c == 0)
            ? x + ((size_t)row * TT + t) * INW + f4 * 4
            : g_out1 + ((size_t)row * TT + (t - 1)) * H1 + (c - 1) * 64 + f4 * 4;
        cp16(aB + (uint32_t)((row * SA1 + c * 64 + f4 * 4) * 4), src);
    }
}

__device__ __forceinline__ void chunk1(const float* sW, const float* sA, int gI, int rp, int c,
                                       ull& a00, ull& a01, ull& a10, ull& a11) {
    const ulonglong2* w0 = (const ulonglong2*)(sW + (2 * gI) * SW1 + c * 64);
    const ulonglong2* w1 = (const ulonglong2*)(sW + (2 * gI + 1) * SW1 + c * 64);
    const ulonglong2* p0 = (const ulonglong2*)(sA + (2 * rp) * SA1 + c * 64);
    const ulonglong2* p1 = (const ulonglong2*)(sA + (2 * rp + 1) * SA1 + c * 64);
#pragma unroll
    for (int i = 0; i < 16; ++i) {
        ulonglong2 W0 = w0[i], W1 = w1[i], A0 = p0[i], A1 = p1[i];
        a00 = fma2(W0.x, A0.x, a00); a01 = fma2(W0.x, A1.x, a01);
        a10 = fma2(W1.x, A0.x, a10); a11 = fma2(W1.x, A1.x, a11);
        a00 = fma2(W0.y, A0.y, a00); a01 = fma2(W0.y, A1.y, a01);
        a10 = fma2(W1.y, A0.y, a10); a11 = fma2(W1.y, A1.y, a11);
    }
}

__global__ void __launch_bounds__(256, 1)
lstm1_kernel(const float* __restrict__ x,
             const float* __restrict__ Wih, const float* __restrict__ Whh,
             const float* __restrict__ bih, const float* __restrict__ bhh,
             float* __restrict__ dout)
{
    extern __shared__ float sm[];
    float* sW = sm;                      // 16*580
    float* sA = sW + 16 * SW1;           // 64*588
    float* sG = sA + 64 * SA1;           // 16*65
    float* sB = sG + 16 * 65;            // 16
    float* sC = sB + 16;                 // 256
    const int tid = threadIdx.x;
    const int bx  = blockIdx.x;

    // stage weights once: row r = gate*4+hcl, cols [x 64 | h 512]
    for (int i = tid; i < 16 * 576; i += 256) {
        int r = i / 576, k = i - r * 576;
        int gr = (r >> 2) * H1 + bx * 4 + (r & 3);
        sW[r * SW1 + k] = (k < INW) ? Wih[gr * INW + k] : Whh[gr * H1 + (k - INW)];
    }
    if (tid < 16) {
        int gr = (tid >> 2) * H1 + bx * 4 + (tid & 3);
        sB[tid] = bih[gr] + bhh[gr];
    }
    sC[tid] = 0.f;
    __syncthreads();

    const int gI = tid & 7;
    const int rp = tid >> 3;
    const uint32_t aB = s2u(sA);

    for (int t = 0; t < TT; ++t) {
        if (t == 0) { load1(0, 0, x, aB); cpcommit(); }
        else {
#pragma unroll
            for (int c = 0; c < 9; ++c) { load1(c, t, x, aB); cpcommit(); }
        }

        ull a00 = 0, a01 = 0, a10 = 0, a11 = 0;
        if (t == 0) {
            cpwait(0); __syncthreads();
            chunk1(sW, sA, gI, rp, 0, a00, a01, a10, a11);
        } else {
#pragma unroll
            for (int c = 0; c < 9; ++c) {
                cpwait(8 - c); __syncthreads();
                chunk1(sW, sA, gI, rp, c, a00, a01, a10, a11);
            }
        }

        // gate exchange
        sG[(2 * gI) * 65 + 2 * rp]         = psum(a00);
        sG[(2 * gI) * 65 + 2 * rp + 1]     = psum(a01);
        sG[(2 * gI + 1) * 65 + 2 * rp]     = psum(a10);
        sG[(2 * gI + 1) * 65 + 2 * rp + 1] = psum(a11);
        __syncthreads();

        // cell update: thread = (n, hcl)
        {
            int n = tid >> 2, hcl = tid & 3;
            float xi = sG[hcl * 65 + n]        + sB[hcl];
            float xf = sG[(4 + hcl) * 65 + n]  + sB[4 + hcl];
            float xg = sG[(8 + hcl) * 65 + n]  + sB[8 + hcl];
            float xo = sG[(12 + hcl) * 65 + n] + sB[12 + hcl];
            float cp = sC[tid];
            float cn = sigf(xf) * cp + sigf(xi) * tanhf(xg);
            sC[tid] = cn;
            float h = sigf(xo) * tanhf(cn);
            int hc = bx * 4 + hcl;
            g_out1[((size_t)n * TT + t) * H1 + hc] = h;
            if (t == TT - 1) {
                dout[65536 + n * H1 + hc] = h;
                dout[98304 + n * H1 + hc] = cn;
            }
        }

        if (t < TT - 1) {
            __threadfence();
            __syncthreads();
            if (tid == 0) {
                atomicAdd(&g_bar1, 1u);
                unsigned tgt = 128u * (unsigned)(t + 1);
                while (*(volatile unsigned*)&g_bar1 < tgt) {}
            }
            __syncthreads();
        }
    }
}

// ============================ LSTM layer 2 ============================
// 128 CTAs x 256 thr. CTA owns 2 hidden cols (8 gate rows), K=768.
// thread: ks=tid>>7 (k-half within chunk), gI=(tid&127)&3, rp=(tid&127)>>2.
__device__ __forceinline__ void load2(int c, int t, uint32_t aB) {
    const int tid = threadIdx.x;
#pragma unroll
    for (int j = 0; j < 4; ++j) {
        int o = j * 256 + tid;
        int row = o >> 4, f4 = o & 15;
        int col = c * 64 + f4 * 4;
        const float* src = (col < 512)
            ? g_out1 + ((size_t)row * TT + t) * H1 + col
            : g_out2 + ((size_t)row * TT + (t - 1)) * H2 + (col - 512);
        cp16(aB + (uint32_t)((row * SA2 + col) * 4), src);
    }
}

__device__ __forceinline__ void chunk2(const float* sW, const float* sA, int gI, int rp, int ks, int c,
                                       ull& a00, ull& a01, ull& a10, ull& a11) {
    const int kb = c * 64 + ks * 32;
    const ulonglong2* w0 = (const ulonglong2*)(sW + (2 * gI) * SW2 + kb);
    const ulonglong2* w1 = (const ulonglong2*)(sW + (2 * gI + 1) * SW2 + kb);
    const ulonglong2* p0 = (const ulonglong2*)(sA + (2 * rp) * SA2 + kb);
    const ulonglong2* p1 = (const ulonglong2*)(sA + (2 * rp + 1) * SA2 + kb);
#pragma unroll
    for (int i = 0; i < 8; ++i) {
        ulonglong2 W0 = w0[i], W1 = w1[i], A0 = p0[i], A1 = p1[i];
        a00 = fma2(W0.x, A0.x, a00); a01 = fma2(W0.x, A1.x, a01);
        a10 = fma2(W1.x, A0.x, a10); a11 = fma2(W1.x, A1.x, a11);
        a00 = fma2(W0.y, A0.y, a00); a01 = fma2(W0.y, A1.y, a01);
        a10 = fma2(W1.y, A0.y, a10); a11 = fma2(W1.y, A1.y, a11);
    }
}

__global__ void __launch_bounds__(256, 1)
lstm2_kernel(const float* __restrict__ Wih, const float* __restrict__ Whh,
             const float* __restrict__ bih, const float* __restrict__ bhh,
             float* __restrict__ dout)
{
    extern __shared__ float sm[];
    float* sW = sm;                      // 8*772
    float* sA = sW + 8 * SW2;            // 64*772
    float* sG = sA + 64 * SA2;           // 16*65 (2 k-halves x 8 rows)
    float* sB = sG + 16 * 65;            // 8
    float* sC = sB + 8;                  // 128
    const int tid = threadIdx.x;
    const int bx  = blockIdx.x;

    for (int i = tid; i < 8 * 768; i += 256) {
        int r = i / 768, k = i - r * 768;
        int gr = (r >> 1) * H2 + bx * 2 + (r & 1);
        sW[r * SW2 + k] = (k < H1) ? Wih[gr * H1 + k] : Whh[gr * H2 + (k - H1)];
    }
    if (tid < 8) {
        int gr = (tid >> 1) * H2 + bx * 2 + (tid & 1);
        sB[tid] = bih[gr] + bhh[gr];
    }
    if (tid < 128) sC[tid] = 0.f;
    __syncthreads();

    const int ks  = tid >> 7;
    const int rem = tid & 127;
    const int gI  = rem & 3;
    const int rp  = rem >> 2;
    const uint32_t aB = s2u(sA);

    for (int t = 0; t < TT; ++t) {
        if (t == 0) {
#pragma unroll
            for (int c = 0; c < 8; ++c) { load2(c, 0, aB); cpcommit(); }
        } else {
#pragma unroll
            for (int c = 0; c < 12; ++c) { load2(c, t, aB); cpcommit(); }
        }

        ull a00 = 0, a01 = 0, a10 = 0, a11 = 0;
        if (t == 0) {
#pragma unroll
            for (int c = 0; c < 8; ++c) {
                cpwait(7 - c); __syncthreads();
                chunk2(sW, sA, gI, rp, ks, c, a00, a01, a10, a11);
            }
        } else {
#pragma unroll
            for (int c = 0; c < 12; ++c) {
                cpwait(11 - c); __syncthreads();
                chunk2(sW, sA, gI, rp, ks, c, a00, a01, a10, a11);
            }
        }

        int base = (ks * 8 + 2 * gI) * 65;
        sG[base + 2 * rp]          = psum(a00);
        sG[base + 2 * rp + 1]      = psum(a01);
        sG[base + 65 + 2 * rp]     = psum(a10);
        sG[base + 65 + 2 * rp + 1] = psum(a11);
        __syncthreads();

        if (tid < 128) {
            int n = tid >> 1, hcl = tid & 1;
            float xi = sG[(0 + hcl) * 65 + n] + sG[(8 + hcl) * 65 + n]  + sB[0 + hcl];
            float xf = sG[(2 + hcl) * 65 + n] + sG[(10 + hcl) * 65 + n] + sB[2 + hcl];
            float xg = sG[(4 + hcl) * 65 + n] + sG[(12 + hcl) * 65 + n] + sB[4 + hcl];
            float xo = sG[(6 + hcl) * 65 + n] + sG[(14 + hcl) * 65 + n] + sB[6 + hcl];
            float cp = sC[tid];
            float cn = sigf(xf) * cp + sigf(xi) * tanhf(xg);
            sC[tid] = cn;
            float h = sigf(xo) * tanhf(cn);
            int hc = bx * 2 + hcl;
            g_out2[((size_t)n * TT + t) * H2 + hc] = h;
            if (t == TT - 1) {
                dout[131072 + n * H2 + hc] = h;
                dout[147456 + n * H2 + hc] = cn;
            }
        }

        if (t < TT - 1) {
            __threadfence();
            __syncthreads();
            if (tid == 0) {
                atomicAdd(&g_bar2, 1u);
                unsigned tgt = 128u * (unsigned)(t + 1);
                while (*(volatile unsigned*)&g_bar2 < tgt) {}
            }
            __syncthreads();
        }
    }
}

// ============================ causal attention ============================
__global__ void __launch_bounds__(256)
attn_kernel()
{
    const int lane = threadIdx.x & 31;
    const int gw = blockIdx.x * (blockDim.x >> 5) + (threadIdx.x >> 5);
    const int nw = gridDim.x * (blockDim.x >> 5);

    for (int row = gw; row < NB * TT; row += nw) {
        const int n = row >> 10;
        const int t = row & 1023;
        const float* bp = g_out2 + (size_t)n * TT * H2;
        const float4* qp = (const float4*)(bp + (size_t)t * H2);
        const float4 qa = qp[lane];
        const float4 qb = qp[lane + 32];

        float m = -1e30f, l = 0.f;
        float4 accA = make_float4(0.f, 0.f, 0.f, 0.f);
        float4 accB = make_float4(0.f, 0.f, 0.f, 0.f);

        for (int s = 0; s <= t; ++s) {
            const float4* kp = (const float4*)(bp + (size_t)s * H2);
            float4 ka = kp[lane];
            float4 kb = kp[lane + 32];
            float p = qa.x*ka.x + qa.y*ka.y + qa.z*ka.z + qa.w*ka.w
                    + qb.x*kb.x + qb.y*kb.y + qb.z*kb.z + qb.w*kb.w;
            p += __shfl_xor_sync(0xffffffffu, p, 16);
            p += __shfl_xor_sync(0xffffffffu, p, 8);
            p += __shfl_xor_sync(0xffffffffu, p, 4);
            p += __shfl_xor_sync(0xffffffffu, p, 2);
            p += __shfl_xor_sync(0xffffffffu, p, 1);
            float nm = fmaxf(m, p);
            float e  = __expf(p - nm);
            float sc = __expf(m - nm);
            l = l * sc + e;
            accA.x = accA.x*sc + e*ka.x; accA.y = accA.y*sc + e*ka.y;
            accA.z = accA.z*sc + e*ka.z; accA.w = accA.w*sc + e*ka.w;
            accB.x = accB.x*sc + e*kb.x; accB.y = accB.y*sc + e*kb.y;
            accB.z = accB.z*sc + e*kb.z; accB.w = accB.w*sc + e*kb.w;
            m = nm;
        }
        float inv = 1.f / l;
        float4* op = (float4*)(g_ctx + (size_t)row * H2);
        op[lane]      = make_float4(accA.x*inv, accA.y*inv, accA.z*inv, accA.w*inv);
        op[lane + 32] = make_float4(accB.x*inv, accB.y*inv, accB.z*inv, accB.w*inv);
    }
}

// ============================ MLP head ============================
__global__ void __launch_bounds__(128)
mlp_kernel(const float* __restrict__ fc1b,
           const float* __restrict__ fc2b,
           const float* __restrict__ fc3w, const float* __restrict__ fc3b,
           float* __restrict__ dout)
{
    __shared__ float sIn[16][512];
    __shared__ float sH1b[16][128];
    __shared__ float sH2b[16][52];
    const int tid = threadIdx.x;

    for (int tile = blockIdx.x; tile < (NB * TT) / 16; tile += gridDim.x) {
        const int row0 = tile * 16;
        for (int i = tid; i < 16 * 512; i += 128) {
            int r = i >> 9, c = i & 511;
            size_t row = (size_t)(row0 + r);
            sIn[r][c] = (c < 256) ? g_ctx[row * 256 + c] : g_out2[row * 256 + (c - 256)];
        }
        __syncthreads();

        {
            float acc[16];
            float b = fc1b[tid];
#pragma unroll
            for (int r = 0; r < 16; ++r) acc[r] = b;
            for (int k = 0; k < 512; ++k) {
                float w = g_fc1T[k * 128 + tid];
#pragma unroll
                for (int r = 0; r < 16; ++r) acc[r] = fmaf(w, sIn[r][k], acc[r]);
            }
#pragma unroll
            for (int r = 0; r < 16; ++r) sH1b[r][tid] = fmaxf(acc[r], 0.f);
        }
        __syncthreads();

        if (tid < 51) {
            float acc[16];
            float b = fc2b[tid];
#pragma unroll
            for (int r = 0; r < 16; ++r) acc[r] = b;
            for (int k = 0; k < 128; ++k) {
                float w = g_fc2T[k * 51 + tid];
#pragma unroll
                for (int r = 0; r < 16; ++r) acc[r] = fmaf(w, sH1b[r][k], acc[r]);
            }
#pragma unroll
            for (int r = 0; r < 16; ++r) sH2b[r][tid] = fmaxf(acc[r], 0.f);
        }
        __syncthreads();

        if (tid < 16) {
            float s = fc3b[0];
            for (int k = 0; k < 51; ++k) s = fmaf(fc3w[k], sH2b[tid][k], s);
            dout[row0 + tid] = s;
        }
        __syncthreads();
    }
}

// ============================ launch ============================
extern "C" void kernel_launch(void* const* d_in, const int* in_sizes, int n_in,
                              void* d_out, int out_size)
{
    const float* x     = (const float*)d_in[0];
    const float* Wih1  = (const float*)d_in[1];
    const float* Whh1  = (const float*)d_in[2];
    const float* bih1  = (const float*)d_in[3];
    const float* bhh1  = (const float*)d_in[4];
    const float* Wih2  = (const float*)d_in[5];
    const float* Whh2  = (const float*)d_in[6];
    const float* bih2  = (const float*)d_in[7];
    const float* bhh2  = (const float*)d_in[8];
    const float* fc1w  = (const float*)d_in[9];
    const float* fc1b  = (const float*)d_in[10];
    const float* fc2w  = (const float*)d_in[11];
    const float* fc2b  = (const float*)d_in[12];
    const float* fc3w  = (const float*)d_in[13];
    const float* fc3b  = (const float*)d_in[14];
    float* out = (float*)d_out;

    const int SM1 = (16 * SW1 + 64 * SA1 + 16 * 65 + 16 + 256) * 4;   // 192,896 B
    const int SM2 = (8 * SW2 + 64 * SA2 + 16 * 65 + 8 + 128) * 4;     // 227,040 B
    cudaFuncSetAttribute(lstm1_kernel, cudaFuncAttributeMaxDynamicSharedMemorySize, SM1);
    cudaFuncSetAttribute(lstm2_kernel, cudaFuncAttributeMaxDynamicSharedMemorySize, SM2);

    reset_kernel<<<1, 1>>>();
    prep_kernel<<<(128 * 512 + 255) / 256, 256>>>(fc1w, fc2w);
    lstm1_kernel<<<128, 256, SM1>>>(x, Wih1, Whh1, bih1, bhh1, out);
    lstm2_kernel<<<128, 256, SM2>>>(Wih2, Whh2, bih2, bhh2, out);
    attn_kernel<<<592, 256>>>();
    mlp_kernel<<<1024, 128>>>(fc1b, fc2b, fc3w, fc3b, out);
}